// round 15
// baseline (speedup 1.0000x reference)
#include <cuda_runtime.h>
#include <math.h>

// FlexibleLogisticModel: f = sigmoid( sum_f w[f]*alpha[ord(f)]*monomial_f(x) ),
// all multiset monomials deg 0..4 in D=64 vars, lex CWR order. Never reads E.
//
// Per-thread fused design: thread gt owns 12 contiguous elements e0=3+12*gt of
// the deg2|deg3|deg4 region (w[65+e] pairs with alpha_d * prod xs[tuple(e)]).
// 3x LDG.128 issued first; one closed-form unrank (branchless fixups); then a
// SPECIALIZED compact 12-step lex walk (pure-deg2/3/4 paths; generic guarded
// path only for the 2 degree-boundary threads + the tail thread). No smem
// operand array, no grid barrier. 133 blocks x 512 = 1 CTA/SM uniform.
// Last block applies sigmoid + resets (graph-replay deterministic).

#define NPAIR 2080
#define N3    45760
#define N4    766480
#define ETOT  814320           // 2080 + 45760 + 766480
#define KPT   12
#define NCH   67860            // ceil((ETOT-3)/12)
#define TPB   512
#define NBLK  133              // ceil(NCH/TPB); 1 CTA/SM, uniform per-SM work

__device__ double   g_acc   = 0.0;
__device__ unsigned g_count = 0;

__device__ __forceinline__ int C2i(int n) { return (n * (n - 1)) >> 1; }
__device__ __forceinline__ int C3i(int n) { return n * (n - 1) * (n - 2) / 6; }
__device__ __forceinline__ int C4i(int n) { return n * (n - 1) * (n - 2) * (n - 3) / 24; }

// smallest n with Ck(n) >= v; starts below true n, fixed predicated fixups
__device__ __forceinline__ int inv_C2(int v) {
    int n = (int)(0.5f * (1.0f + sqrtf(8.0f * (float)v + 1.0f))) - 1;
    if (n < 2) n = 2;
    n += (C2i(n) < v); n += (C2i(n) < v); n += (C2i(n) < v);
    return n;
}
__device__ __forceinline__ int inv_C3(int v) {
    int n = (int)cbrtf(6.0f * (float)v) - 1;
    if (n < 3) n = 3;
    n += (C3i(n) < v); n += (C3i(n) < v);
    n += (C3i(n) < v); n += (C3i(n) < v);
    return n;
}
__device__ __forceinline__ int inv_C4(int v) {
    int n = (int)sqrtf(sqrtf(24.0f * (float)v)) - 1;
    if (n < 4) n = 4;
    n += (C4i(n) < v); n += (C4i(n) < v); n += (C4i(n) < v);
    n += (C4i(n) < v); n += (C4i(n) < v);
    return n;
}

__global__ void __launch_bounds__(TPB, 1)
poly_fused_kernel(const float* __restrict__ x,
                  const float* __restrict__ w,
                  const float* __restrict__ alphas,
                  float* __restrict__ out)
{
    __shared__ float  xs[68];      // padded: xs[64..67] = 0 (OOB-carry safety)
    __shared__ float  al[5];
    __shared__ double warp_sums[TPB / 32];

    const int tid  = threadIdx.x;
    const int bid  = blockIdx.x;
    const int lane = tid & 31;
    if (tid < 68) xs[tid] = (tid < 64) ? x[tid] : 0.0f;
    if (tid < 5)  al[tid] = alphas[tid];
    __syncthreads();

    const float A2 = al[2], A3 = al[3], A4 = al[4];
    const int gt = bid * TPB + tid;
    double local = 0.0;

    if (gt < NCH) {
        const int e0   = 3 + KPT * gt;
        const int eL   = e0 + KPT - 1;
        const bool tail = (eL >= ETOT);          // only the very last chunk

        // ---- issue w loads first (3x LDG.128; (65+e0) % 4 == 0) ----
        float wa[KPT];
        if (!tail) {
            const float4* __restrict__ wv = (const float4*)(w + 65 + e0);
            const float4 v0 = wv[0], v1 = wv[1], v2 = wv[2];
            wa[0]=v0.x; wa[1]=v0.y; wa[2]=v0.z; wa[3]=v0.w;
            wa[4]=v1.x; wa[5]=v1.y; wa[6]=v1.z; wa[7]=v1.w;
            wa[8]=v2.x; wa[9]=v2.y; wa[10]=v2.z; wa[11]=v2.w;
        } else {
            #pragma unroll
            for (int k = 0; k < KPT; ++k)
                wa[k] = (e0 + k < ETOT) ? w[65 + e0 + k] : 0.0f;
        }

        float s0 = 0.f, s1 = 0.f, s2 = 0.f, s3 = 0.f;

        if (!tail && eL < NPAIR) {
            // ======== pure deg-2 chunk ========
            const int rem = NPAIR - e0;
            const int n = inv_C2(rem);
            int v0i = 65 - n;
            int last = v0i + (C2i(n) - rem);
            float pre = A2 * xs[v0i];
            #pragma unroll
            for (int k = 0; k < KPT; ++k) {
                const float p = pre * xs[last];
                if ((k & 3) == 0) s0 += wa[k] * p;
                else if ((k & 3) == 1) s1 += wa[k] * p;
                else if ((k & 3) == 2) s2 += wa[k] * p;
                else s3 += wa[k] * p;
                if (++last == 64) { ++v0i; last = v0i; pre = A2 * xs[v0i]; }
            }
        } else if (!tail && e0 >= NPAIR && eL < NPAIR + N3) {
            // ======== pure deg-3 chunk ========
            const int rem = N3 - (e0 - NPAIR);
            const int b = inv_C3(rem);
            int v0i = 66 - b;
            const int kk = C3i(b) - rem;
            const int remp = C2i(65 - v0i) - kk;
            const int n = inv_C2(remp);
            int v1i = 65 - n;
            int last = v1i + (C2i(n) - remp);
            float pre = A3 * xs[v0i] * xs[v1i];
            #pragma unroll
            for (int k = 0; k < KPT; ++k) {
                const float p = pre * xs[last];
                if ((k & 3) == 0) s0 += wa[k] * p;
                else if ((k & 3) == 1) s1 += wa[k] * p;
                else if ((k & 3) == 2) s2 += wa[k] * p;
                else s3 += wa[k] * p;
                if (++last == 64) {
                    if (++v1i == 64) { ++v0i; v1i = v0i; }
                    last = v1i;
                    pre = A3 * xs[v0i] * xs[v1i];
                }
            }
        } else if (!tail && e0 >= NPAIR + N3) {
            // ======== pure deg-4 chunk ========
            const int rem = N4 - (e0 - NPAIR - N3);
            const int a = inv_C4(rem);
            int v0i = 67 - a;
            const int r1 = C4i(a) - rem;
            const int rem3 = C3i(66 - v0i) - r1;
            const int b = inv_C3(rem3);
            int v1i = 66 - b;
            const int kk = C3i(b) - rem3;
            const int remp = C2i(65 - v1i) - kk;
            const int n = inv_C2(remp);
            int v2i = 65 - n;
            int last = v2i + (C2i(n) - remp);
            float pre = A4 * xs[v0i] * xs[v1i] * xs[v2i];
            #pragma unroll
            for (int k = 0; k < KPT; ++k) {
                const float p = pre * xs[last];
                if ((k & 3) == 0) s0 += wa[k] * p;
                else if ((k & 3) == 1) s1 += wa[k] * p;
                else if ((k & 3) == 2) s2 += wa[k] * p;
                else s3 += wa[k] * p;
                if (++last == 64) {
                    if (++v2i == 64) {
                        if (++v1i == 64) { ++v0i; v1i = v0i; }
                        v2i = v1i;
                    }
                    last = v2i;
                    pre = A4 * xs[v0i] * xs[v1i] * xs[v2i];
                }
            }
        } else {
            // ======== generic guarded path (2 boundary threads + tail) ========
            int d, v0i = 0, v1i = 0, v2i = 0, last;
            float pre;
            if (e0 < NPAIR) {
                d = 2;
                const int rem = NPAIR - e0;
                const int n = inv_C2(rem);
                v0i = 65 - n; last = v0i + (C2i(n) - rem);
                pre = A2 * xs[v0i];
            } else if (e0 < NPAIR + N3) {
                d = 3;
                const int rem = N3 - (e0 - NPAIR);
                const int b = inv_C3(rem);
                v0i = 66 - b;
                const int kk = C3i(b) - rem;
                const int remp = C2i(65 - v0i) - kk;
                const int n = inv_C2(remp);
                v1i = 65 - n; last = v1i + (C2i(n) - remp);
                pre = A3 * xs[v0i] * xs[v1i];
            } else {
                d = 4;
                const int rem = N4 - (e0 - NPAIR - N3);
                const int a = inv_C4(rem);
                v0i = 67 - a;
                const int r1 = C4i(a) - rem;
                const int rem3 = C3i(66 - v0i) - r1;
                const int b = inv_C3(rem3);
                v1i = 66 - b;
                const int kk = C3i(b) - rem3;
                const int remp = C2i(65 - v1i) - kk;
                const int n = inv_C2(remp);
                v2i = 65 - n; last = v2i + (C2i(n) - remp);
                pre = A4 * xs[v0i] * xs[v1i] * xs[v2i];
            }
            int e = e0;
            #pragma unroll 1
            for (int k = 0; k < KPT; ++k, ++e) {
                if (e < ETOT) {
                    const float p = pre * xs[last];
                    s0 += wa[k] * p;
                    if (last < 63) { ++last; }
                    else if (d == 2) {
                        if (v0i < 63) { ++v0i; last = v0i; pre = A2 * xs[v0i]; }
                        else { d = 3; v0i = v1i = 0; last = 0;
                               pre = A3 * xs[0] * xs[0]; }
                    } else if (d == 3) {
                        if (v1i < 63)      { ++v1i; last = v1i; pre = A3 * xs[v0i] * xs[v1i]; }
                        else if (v0i < 63) { ++v0i; v1i = v0i; last = v0i;
                                             pre = A3 * xs[v0i] * xs[v1i]; }
                        else { d = 4; v0i = v1i = v2i = 0; last = 0;
                               pre = A4 * xs[0] * xs[0] * xs[0]; }
                    } else {
                        if (v2i < 63)      { ++v2i; last = v2i; pre = A4 * xs[v0i] * xs[v1i] * xs[v2i]; }
                        else if (v1i < 63) { ++v1i; v2i = v1i; last = v1i;
                                             pre = A4 * xs[v0i] * xs[v1i] * xs[v2i]; }
                        else if (v0i < 63) { ++v0i; v1i = v2i = v0i; last = v0i;
                                             pre = A4 * xs[v0i] * xs[v1i] * xs[v2i]; }
                        // past (63,63,63,63): state frozen; e-guard ends loop
                    }
                }
            }
        }
        local = (double)((s0 + s1) + (s2 + s3));
    }

    // ---- deg-0/1 + first 3 deg-2 elements (block 0, warp 0) ----
    if (bid == 0 && tid < 32) {
        float s = al[1] * (w[1 + lane] * xs[lane] + w[33 + lane] * xs[32 + lane]);
        if (lane == 0) {
            s += al[0] * w[0];
            s += A2 * xs[0] * (w[65] * xs[0] + w[66] * xs[1] + w[67] * xs[2]);
        }
        local += (double)s;
    }

    // ---- warp + block reduction (double) ----
    #pragma unroll
    for (int o = 16; o > 0; o >>= 1)
        local += __shfl_down_sync(0xffffffffu, local, o);
    if (lane == 0) warp_sums[tid >> 5] = local;
    __syncthreads();

    if (tid == 0) {
        double bs = 0.0;
        #pragma unroll
        for (int i = 0; i < TPB / 32; i++) bs += warp_sums[i];
        atomicAdd(&g_acc, bs);
        __threadfence();
        const unsigned done = atomicAdd(&g_count, 1u);
        if (done == NBLK - 1) {
            const double a = atomicAdd(&g_acc, 0.0);   // all contributions visible
            out[0] = (float)(1.0 / (1.0 + exp(-a)));
            g_acc   = 0.0;   // reset for next graph replay
            g_count = 0u;
        }
    }
}

extern "C" void kernel_launch(void* const* d_in, const int* in_sizes, int n_in,
                              void* d_out, int out_size)
{
    const float* x      = (const float*)d_in[0];
    const float* w      = (const float*)d_in[1];
    const float* alphas = (const float*)d_in[2];
    // d_in[3] = E (constant, NOT read), d_in[4] = ord_ids (NOT read)
    float* out = (float*)d_out;

    poly_fused_kernel<<<NBLK, TPB>>>(x, w, alphas, out);
}

// round 17
// speedup vs baseline: 1.0185x; 1.0185x over previous
#include <cuda_runtime.h>
#include <math.h>

// FlexibleLogisticModel: f = sigmoid( sum_f w[f]*alpha[ord(f)]*monomial_f(x) ),
// all multiset monomials deg 0..4 in D=64 vars, lex CWR order. Never reads E.
//
// Thread gt owns 12 contiguous elements e0=3+12*gt of the deg2|deg3|deg4
// region (w[65+e] pairs with alpha_d * prod xs[tuple]). 3x LDG.128 first.
// Multiplier factored M = preH * xs[a] * xs[b]; preH is constant across the
// chunk when the chunk stays inside one hi-block (test: remp >= 12, ~97% of
// threads). Fast path: integer-only (a,b) walk -> 24 BATCHED LDS -> FMA tree
// (breaks the serial 29-cyc-per-step LDS chain of the naive walk). Boundary/
// tail threads use the guarded generic walk. Block sums -> atomicAdd; last
// block applies sigmoid + resets (graph-replay deterministic).

#define NPAIR 2080
#define N3    45760
#define N4    766480
#define ETOT  814320           // 2080 + 45760 + 766480
#define KPT   12
#define NCH   67860            // ceil((ETOT-3)/12)
#define TPB   256
#define NBLK  266              // ceil(NCH/TPB)

__device__ double   g_acc   = 0.0;
__device__ unsigned g_count = 0;

__device__ __forceinline__ int C2i(int n) { return (n * (n - 1)) >> 1; }
__device__ __forceinline__ int C3i(int n) { return n * (n - 1) * (n - 2) / 6; }
__device__ __forceinline__ int C4i(int n) { return n * (n - 1) * (n - 2) * (n - 3) / 24; }

// smallest n with Ck(n) >= v; start below, fixed predicated fixups
__device__ __forceinline__ int inv_C2(int v) {
    int n = (int)(0.5f * (1.0f + sqrtf(8.0f * (float)v + 1.0f))) - 1;
    if (n < 2) n = 2;
    n += (C2i(n) < v); n += (C2i(n) < v); n += (C2i(n) < v);
    return n;
}
__device__ __forceinline__ int inv_C3(int v) {
    int n = (int)cbrtf(6.0f * (float)v) - 1;
    if (n < 3) n = 3;
    n += (C3i(n) < v); n += (C3i(n) < v);
    n += (C3i(n) < v); n += (C3i(n) < v);
    return n;
}
__device__ __forceinline__ int inv_C4(int v) {
    int n = (int)sqrtf(sqrtf(24.0f * (float)v)) - 1;
    if (n < 4) n = 4;
    n += (C4i(n) < v); n += (C4i(n) < v); n += (C4i(n) < v);
    n += (C4i(n) < v); n += (C4i(n) < v);
    return n;
}

__global__ void __launch_bounds__(TPB, 2)
poly_fused_kernel(const float* __restrict__ x,
                  const float* __restrict__ w,
                  const float* __restrict__ alphas,
                  float* __restrict__ out)
{
    __shared__ float  xs[68];      // xs[64..67] = 0 (slow-path safety)
    __shared__ float  al[5];
    __shared__ double warp_sums[TPB / 32];

    const int tid  = threadIdx.x;
    const int bid  = blockIdx.x;
    const int lane = tid & 31;
    if (tid < 68) xs[tid] = (tid < 64) ? x[tid] : 0.0f;
    if (tid < 5)  al[tid] = alphas[tid];
    __syncthreads();

    const float A2 = al[2], A3 = al[3], A4 = al[4];
    const int gt = bid * TPB + tid;
    double local = 0.0;

    if (gt < NCH) {
        const int e0 = 3 + KPT * gt;

        // ---- issue w loads first (3x LDG.128; (65+e0) % 4 == 0) ----
        float wa[KPT];
        if (e0 + KPT <= ETOT) {
            const float4* __restrict__ wv = (const float4*)(w + 65 + e0);
            const float4 v0 = wv[0], v1 = wv[1], v2 = wv[2];
            wa[0]=v0.x; wa[1]=v0.y; wa[2]=v0.z; wa[3]=v0.w;
            wa[4]=v1.x; wa[5]=v1.y; wa[6]=v1.z; wa[7]=v1.w;
            wa[8]=v2.x; wa[9]=v2.y; wa[10]=v2.z; wa[11]=v2.w;
        } else {
            #pragma unroll
            for (int k = 0; k < KPT; ++k)
                wa[k] = (e0 + k < ETOT) ? w[65 + e0 + k] : 0.0f;
        }

        // ---- unrank e0; compute (preH, a, b) and remaining-in-hi-block ----
        int d, v0i = 0, v1i = 0, v2i = 0, last, remHi;
        float preH;
        if (e0 < NPAIR) {                          // deg2: tuple (v0, last)
            d = 2;
            const int rem = NPAIR - e0;
            const int n = inv_C2(rem);
            v0i = 65 - n; last = v0i + (C2i(n) - rem);
            preH = A2;
            remHi = rem;                           // stays fast iff all in deg2
        } else if (e0 < NPAIR + N3) {              // deg3: (v0, v1, last)
            d = 3;
            const int rem = N3 - (e0 - NPAIR);
            const int b = inv_C3(rem);
            v0i = 66 - b;
            const int kk = C3i(b) - rem;
            const int remp = C2i(65 - v0i) - kk;   // remaining in v0-block (incl)
            const int n = inv_C2(remp);
            v1i = 65 - n; last = v1i + (C2i(n) - remp);
            preH = A3 * xs[v0i];
            remHi = remp;
        } else {                                   // deg4: (v0, v1, v2, last)
            d = 4;
            const int rem = N4 - (e0 - NPAIR - N3);
            const int a = inv_C4(rem);
            v0i = 67 - a;
            const int r1 = C4i(a) - rem;
            const int rem3 = C3i(66 - v0i) - r1;
            const int b = inv_C3(rem3);
            v1i = 66 - b;
            const int kk = C3i(b) - rem3;
            const int remp = C2i(65 - v1i) - kk;   // remaining in v1-block (incl)
            const int n = inv_C2(remp);
            v2i = 65 - n; last = v2i + (C2i(n) - remp);
            preH = A4 * xs[v0i] * xs[v1i];
            remHi = remp;
        }

        if (remHi >= KPT) {
            // ======== FAST PATH: preH constant; break the LDS chain ========
            int a = (d == 2) ? v0i : ((d == 3) ? v1i : v2i);
            int b = last;
            int ia[KPT], ib[KPT];
            #pragma unroll
            for (int k = 0; k < KPT; ++k) {        // integer-only walk
                ia[k] = a; ib[k] = b;
                if (++b == 64) { b = ++a; }        // a < 64 guaranteed
            }
            float t[KPT];
            #pragma unroll
            for (int k = 0; k < KPT; ++k)          // 24 batched LDS + 12 FMUL
                t[k] = xs[ia[k]] * xs[ib[k]];
            float s0 = 0.f, s1 = 0.f, s2 = 0.f, s3 = 0.f;
            #pragma unroll
            for (int k = 0; k < KPT; k += 4) {
                s0 += wa[k]     * t[k];
                s1 += wa[k + 1] * t[k + 1];
                s2 += wa[k + 2] * t[k + 2];
                s3 += wa[k + 3] * t[k + 3];
            }
            local = (double)(preH * ((s0 + s1) + (s2 + s3)));
        } else {
            // ======== SLOW PATH (hi-block / degree boundary, tail) ========
            float pre = (d == 2) ? A2 * xs[v0i]
                       : (d == 3) ? A3 * xs[v0i] * xs[v1i]
                                  : A4 * xs[v0i] * xs[v1i] * xs[v2i];
            float s0 = 0.f;
            int e = e0;
            #pragma unroll 1
            for (int k = 0; k < KPT; ++k, ++e) {
                if (e < ETOT) {
                    s0 += wa[k] * (pre * xs[last]);
                    if (last < 63) { ++last; }
                    else if (d == 2) {
                        if (v0i < 63) { ++v0i; last = v0i; pre = A2 * xs[v0i]; }
                        else { d = 3; v0i = v1i = 0; last = 0;
                               pre = A3 * xs[0] * xs[0]; }
                    } else if (d == 3) {
                        if (v1i < 63)      { ++v1i; last = v1i; pre = A3 * xs[v0i] * xs[v1i]; }
                        else if (v0i < 63) { ++v0i; v1i = v0i; last = v0i;
                                             pre = A3 * xs[v0i] * xs[v1i]; }
                        else { d = 4; v0i = v1i = v2i = 0; last = 0;
                               pre = A4 * xs[0] * xs[0] * xs[0]; }
                    } else {
                        if (v2i < 63)      { ++v2i; last = v2i; pre = A4 * xs[v0i] * xs[v1i] * xs[v2i]; }
                        else if (v1i < 63) { ++v1i; v2i = v1i; last = v1i;
                                             pre = A4 * xs[v0i] * xs[v1i] * xs[v2i]; }
                        else if (v0i < 63) { ++v0i; v1i = v2i = v0i; last = v0i;
                                             pre = A4 * xs[v0i] * xs[v1i] * xs[v2i]; }
                        // past (63,63,63,63): e-guard ends loop
                    }
                }
            }
            local = (double)s0;
        }
    }

    // ---- deg-0/1 + first 3 deg-2 elements (block 0, warp 0) ----
    if (bid == 0 && tid < 32) {
        float s = al[1] * (w[1 + lane] * xs[lane] + w[33 + lane] * xs[32 + lane]);
        if (lane == 0) {
            s += al[0] * w[0];
            s += A2 * xs[0] * (w[65] * xs[0] + w[66] * xs[1] + w[67] * xs[2]);
        }
        local += (double)s;
    }

    // ---- warp + block reduction (double) ----
    #pragma unroll
    for (int o = 16; o > 0; o >>= 1)
        local += __shfl_down_sync(0xffffffffu, local, o);
    if (lane == 0) warp_sums[tid >> 5] = local;
    __syncthreads();

    if (tid == 0) {
        double bs = 0.0;
        #pragma unroll
        for (int i = 0; i < TPB / 32; i++) bs += warp_sums[i];
        atomicAdd(&g_acc, bs);
        __threadfence();
        const unsigned done = atomicAdd(&g_count, 1u);
        if (done == NBLK - 1) {
            const double a = atomicAdd(&g_acc, 0.0);   // all contributions visible
            out[0] = (float)(1.0 / (1.0 + exp(-a)));
            g_acc   = 0.0;   // reset for next graph replay
            g_count = 0u;
        }
    }
}

extern "C" void kernel_launch(void* const* d_in, const int* in_sizes, int n_in,
                              void* d_out, int out_size)
{
    const float* x      = (const float*)d_in[0];
    const float* w      = (const float*)d_in[1];
    const float* alphas = (const float*)d_in[2];
    // d_in[3] = E (constant, NOT read), d_in[4] = ord_ids (NOT read)
    float* out = (float*)d_out;

    poly_fused_kernel<<<NBLK, TPB>>>(x, w, alphas, out);
}